// round 16
// baseline (speedup 1.0000x reference)
#include <cuda_runtime.h>
#include <math.h>

#define NPTS   4096
#define NB     16
#define NARR   32           // 16 batches x 2 directions
#define D      3
#define NEL    (NPTS * D)   // 12288 residual elements per array
#define GR     16           // grid resolution per axis
#define NCELL  (GR * GR * GR)
#define GRIDN  128          // persistent-kernel grid size (co-resident)

// Scratch (device globals only; no allocation allowed)
__device__ float4       g_sorted[(size_t)NARR * NPTS];      // {x,y,z,_}
__device__ int          g_cellstart[(size_t)NARR * (NCELL + 1)];
__device__ int          g_hist[(size_t)NARR * 4 * NCELL];   // hist -> qbase (in place)
__device__ unsigned int g_keys[(size_t)NARR * NEL];         // SoA radix keys
__device__ float        g_sigma[NARR];
__device__ unsigned int g_bar[4];                           // ticket barriers
__device__ int          g_done;                             // self-reset

// ---------------------------------------------------------------------------
// Replay-safe device-wide barrier (monotonic tickets, no reset needed).
// ---------------------------------------------------------------------------
__device__ __forceinline__ void grid_barrier(unsigned int* bar)
{
    __syncthreads();
    if (threadIdx.x == 0) {
        __threadfence();
        unsigned int ticket = atomicAdd(bar, 1u);
        unsigned int target = ticket - (ticket % GRIDN) + GRIDN;
        while (*((volatile unsigned int*)bar) < target) __nanosleep(32);
        __threadfence();
    }
    __syncthreads();
}

// ---------------------------------------------------------------------------
// Block reductions for 1024 threads (32 warps)
// ---------------------------------------------------------------------------
__device__ __forceinline__ float blockSum1024(float v, float* sb, int tid)
{
#pragma unroll
    for (int o = 16; o; o >>= 1) v += __shfl_down_sync(0xffffffffu, v, o);
    if ((tid & 31) == 0) sb[tid >> 5] = v;
    __syncthreads();
    if (tid < 32) {
        float w = sb[tid];
#pragma unroll
        for (int o = 16; o; o >>= 1) w += __shfl_down_sync(0xffffffffu, w, o);
        if (tid == 0) sb[0] = w;
    }
    __syncthreads();
    float r = sb[0];
    __syncthreads();
    return r;
}

__device__ __forceinline__ unsigned int blockMin1024(unsigned int v,
                                                     unsigned int* sb, int tid)
{
#pragma unroll
    for (int o = 16; o; o >>= 1)
        v = min(v, __shfl_down_sync(0xffffffffu, v, o));
    if ((tid & 31) == 0) sb[tid >> 5] = v;
    __syncthreads();
    if (tid < 32) {
        unsigned int w = sb[tid];
#pragma unroll
        for (int o = 16; o; o >>= 1)
            w = min(w, __shfl_down_sync(0xffffffffu, w, o));
        if (tid == 0) sb[0] = w;
    }
    __syncthreads();
    unsigned int r = sb[0];
    __syncthreads();
    return r;
}

__device__ __forceinline__ float key_to_float(unsigned int u)
{
    u = (u & 0x80000000u) ? (u ^ 0x80000000u) : ~u;
    return __uint_as_float(u);
}

__device__ __forceinline__ void scan256(int* hh, int lane)
{
    int base = lane * 8;
    int loc[8];
    int s = 0;
#pragma unroll
    for (int j = 0; j < 8; j++) { s += hh[base + j]; loc[j] = s; }
    int incl = s;
#pragma unroll
    for (int o = 1; o < 32; o <<= 1) {
        int up = __shfl_up_sync(0xffffffffu, incl, o);
        if (lane >= o) incl += up;
    }
    int excl = incl - s;
#pragma unroll
    for (int j = 0; j < 8; j++) hh[base + j] = loc[j] + excl;
}

// ---------------------------------------------------------------------------
// ONE persistent kernel.
// Phase A (parallel build, 4 blocks/set):
//   A1: per-quarter smem histogram -> g_hist[set][quarter]     (all blocks)
//   A2: per-set scan -> g_cellstart + in-place quarter bases   (32 blocks)
//   A3: per-quarter atomic scatter into g_sorted               (all blocks)
// Phase B: grid NN query (all 128 blocks, 1 query/thread)
// Phase C: robust std (blocks 0..31) + atomic finalize.
// ---------------------------------------------------------------------------
__global__ __launch_bounds__(1024) void fused_kernel(
    const float* __restrict__ x, const float* __restrict__ y,
    float* __restrict__ out)
{
    extern __shared__ unsigned int uv[];     // 48KB, Phase C keys
    __shared__ int s_cnt[NCELL];             // 16KB, build histogram / bases
    __shared__ int s_wsum[32];
    __shared__ int h0[256], h1[256];
    __shared__ float sbuf[32];
    __shared__ volatile unsigned int sh4[4];

    const int tid = threadIdx.x;             // 1024 threads
    const int blk = blockIdx.x;              // 0..127
    const int set     = blk >> 2;            // 0..31
    const int quarter = blk & 3;

    // ======================= Phase A1: quarter histograms =====================
    float px, py, pz;
    int   cid;
    {
        const int batch = set >> 1;
        const int which = set & 1;
        const float* P = ((which == 0) ? x : y) + (size_t)batch * NPTS * D;
        const int ptidx = quarter * 1024 + tid;

        px = P[3 * ptidx + 0];
        py = P[3 * ptidx + 1];
        pz = P[3 * ptidx + 2];

#pragma unroll
        for (int j = 0; j < 4; j++) s_cnt[tid + j * 1024] = 0;
        __syncthreads();

        int cx = min(GR - 1, max(0, (int)(px * (float)GR)));
        int cy = min(GR - 1, max(0, (int)(py * (float)GR)));
        int cz = min(GR - 1, max(0, (int)(pz * (float)GR)));
        cid = (cz * GR + cy) * GR + cx;
        atomicAdd(&s_cnt[cid], 1);
        __syncthreads();

        const size_t hbase = ((size_t)set * 4 + quarter) * NCELL;
#pragma unroll
        for (int j = 0; j < 4; j++)
            g_hist[hbase + tid + j * 1024] = s_cnt[tid + j * 1024];
    }

    grid_barrier(&g_bar[0]);

    // ======================= Phase A2: per-set scan (quarter 0 only) =========
    if (quarter == 0) {
        const size_t hb = (size_t)set * 4 * NCELL;
        const int base = tid * 4;
        int a0[4], a1[4], a2[4], tot[4], loc[4];
#pragma unroll
        for (int j = 0; j < 4; j++) {
            int c = base + j;
            a0[j] = g_hist[hb + 0 * NCELL + c];
            a1[j] = g_hist[hb + 1 * NCELL + c];
            a2[j] = g_hist[hb + 2 * NCELL + c];
            int a3 = g_hist[hb + 3 * NCELL + c];
            tot[j] = a0[j] + a1[j] + a2[j] + a3;
        }
        int s = 0;
#pragma unroll
        for (int j = 0; j < 4; j++) { loc[j] = s; s += tot[j]; }
        int incl = s;
#pragma unroll
        for (int o = 1; o < 32; o <<= 1) {
            int u = __shfl_up_sync(0xffffffffu, incl, o);
            if ((tid & 31) >= o) incl += u;
        }
        if ((tid & 31) == 31) s_wsum[tid >> 5] = incl;
        __syncthreads();
        if (tid < 32) {
            int v = s_wsum[tid];
#pragma unroll
            for (int o = 1; o < 32; o <<= 1) {
                int u = __shfl_up_sync(0xffffffffu, v, o);
                if (tid >= o) v += u;
            }
            s_wsum[tid] = v;
        }
        __syncthreads();
        int wexcl = (tid >= 32) ? s_wsum[(tid >> 5) - 1] : 0;
        int texcl = (incl - s) + wexcl;

        const int gbase = set * (NCELL + 1);
#pragma unroll
        for (int j = 0; j < 4; j++) {
            int c  = base + j;
            int st = texcl + loc[j];
            g_cellstart[gbase + c] = st;
            g_hist[hb + 0 * NCELL + c] = st;                       // qbase q0
            g_hist[hb + 1 * NCELL + c] = st + a0[j];               // qbase q1
            g_hist[hb + 2 * NCELL + c] = st + a0[j] + a1[j];       // qbase q2
            g_hist[hb + 3 * NCELL + c] = st + a0[j] + a1[j] + a2[j];
        }
        if (tid == 0) g_cellstart[gbase + NCELL] = NPTS;
    }

    grid_barrier(&g_bar[1]);

    // ======================= Phase A3: quarter scatter ========================
    {
        const size_t hbase = ((size_t)set * 4 + quarter) * NCELL;
#pragma unroll
        for (int j = 0; j < 4; j++)
            s_cnt[tid + j * 1024] = g_hist[hbase + tid + j * 1024];
        __syncthreads();

        int off = atomicAdd(&s_cnt[cid], 1);
        g_sorted[(size_t)set * NPTS + off] = make_float4(px, py, pz, 0.f);
    }

    grid_barrier(&g_bar[2]);

    // ======================= Phase B: grid NN query ==========================
    {
        const int gtid = blk * 1024 + tid;        // 0..131071
        const int arr  = gtid >> 12;              // /NPTS
        const int i    = gtid & (NPTS - 1);       // sorted query index
        const int tset = arr ^ 1;

        float4 q = g_sorted[(size_t)arr * NPTS + i];
        const float4* __restrict__ T  = g_sorted + (size_t)tset * NPTS;
        const int* __restrict__    cs = g_cellstart + (size_t)tset * (NCELL + 1);

        const int cx = min(GR - 1, max(0, (int)(q.x * (float)GR)));
        const int cy = min(GR - 1, max(0, (int)(q.y * (float)GR)));
        const int cz = min(GR - 1, max(0, (int)(q.z * (float)GR)));

        const float h = 1.0f / (float)GR;
        float best = __int_as_float(0x7f800000);
        float bx = 0.f, by = 0.f, bz = 0.f;

        auto process = [&](float4 p) {
            float dx = q.x - p.x, dy = q.y - p.y, dz = q.z - p.z;
            float d2 = fmaf(dx, dx, fmaf(dy, dy, dz * dz));
            if (d2 < best) { best = d2; bx = p.x; by = p.y; bz = p.z; }
        };

        // merged rings 0+1: 3x3 rows, all bounds prefetched (MLP)
        {
            const int xlo = max(cx - 1, 0), xhi = min(cx + 1, GR - 1);
            int rs[9], re[9];
#pragma unroll
            for (int k = 0; k < 9; k++) {
                int dz = k / 3 - 1, dy = k % 3 - 1;
                int zz = cz + dz, yy = cy + dy;
                bool ok = (zz >= 0) && (zz < GR) && (yy >= 0) && (yy < GR);
                int rowb = (zz * GR + yy) * GR;
                rs[k] = ok ? cs[rowb + xlo] : 0;
                re[k] = ok ? cs[rowb + xhi + 1] : 0;
            }
#pragma unroll
            for (int k = 0; k < 9; k++)
                for (int j = rs[k]; j < re[k]; j++) process(T[j]);
        }

        // rare fallback: rings r >= 2
        if (best > h * h) {
            for (int r = 2; r < GR; r++) {
                int zlo = max(cz - r, 0), zhi = min(cz + r, GR - 1);
                int xlo = max(cx - r, 0), xhi = min(cx + r, GR - 1);
                for (int zz = zlo; zz <= zhi; zz++) {
                    bool zface = (zz == cz - r) || (zz == cz + r);
                    int ylo = max(cy - r, 0), yhi = min(cy + r, GR - 1);
                    for (int yy = ylo; yy <= yhi; yy++) {
                        bool yface = (yy == cy - r) || (yy == cy + r);
                        int rowb = (zz * GR + yy) * GR;
                        if (zface || yface) {
                            int s0 = cs[rowb + xlo], s1 = cs[rowb + xhi + 1];
                            for (int j = s0; j < s1; j++) process(T[j]);
                        } else {
                            int xm = cx - r;
                            if (xm >= 0) {
                                int s0 = cs[rowb + xm], s1 = cs[rowb + xm + 1];
                                for (int j = s0; j < s1; j++) process(T[j]);
                            }
                            int xp = cx + r;
                            if (xp <= GR - 1) {
                                int s0 = cs[rowb + xp], s1 = cs[rowb + xp + 1];
                                for (int j = s0; j < s1; j++) process(T[j]);
                            }
                        }
                    }
                }
                float bnd = (float)r * h;
                if (best <= bnd * bnd) break;
            }
        }

        // residual -> order-preserving radix keys, SoA coalesced stores
        unsigned int ux = __float_as_uint(q.x - bx);
        unsigned int uy = __float_as_uint(q.y - by);
        unsigned int uz = __float_as_uint(q.z - bz);
        ux = (ux & 0x80000000u) ? ~ux : (ux | 0x80000000u);
        uy = (uy & 0x80000000u) ? ~uy : (uy | 0x80000000u);
        uz = (uz & 0x80000000u) ? ~uz : (uz | 0x80000000u);
        unsigned int* gk = g_keys + (size_t)arr * NEL;
        gk[0 * NPTS + i] = ux;
        gk[1 * NPTS + i] = uy;
        gk[2 * NPTS + i] = uz;
    }

    grid_barrier(&g_bar[3]);

    if (blk >= NARR) return;

    // ======================= Phase C: robust masked std ======================
    const int arr = blk;
    const int T   = 1024;
    const unsigned int* gk = g_keys + (size_t)arr * NEL;

#pragma unroll
    for (int j = 0; j < NEL / 1024; j++) {
        int i = tid + j * 1024;
        uv[i] = gk[i];
    }
    __syncthreads();

    const float n1 = (float)(NEL - 1);
    float hlo = 0.15f * n1;  int ilo = (int)hlo;  float flo = hlo - (float)ilo;
    float hhi = 0.85f * n1;  int ihi = (int)hhi;  float fhi = hhi - (float)ihi;

    // ---- dual-rank radix select ----------------------------------------------
    unsigned int plo = 0, phi = 0, pmask = 0;
    int kl = ilo, kh = ihi;
    for (int shift = 24; shift >= 0; shift -= 8) {
        bool same = (plo == phi);
        if (tid < 256) { h0[tid] = 0; h1[tid] = 0; }
        __syncthreads();
#pragma unroll
        for (int j = 0; j < NEL / 1024; j++) {
            unsigned int u = uv[tid + j * 1024];
            if ((u & pmask) == plo) atomicAdd(&h0[(u >> shift) & 255], 1);
            if (!same && (u & pmask) == phi)
                atomicAdd(&h1[(u >> shift) & 255], 1);
        }
        __syncthreads();
        if (tid < 32) scan256(h0, tid);
        else if (tid < 64 && !same) scan256(h1, tid - 32);
        __syncthreads();
        if (tid < 256) {
            int hi = h0[tid];
            int lo = tid ? h0[tid - 1] : 0;
            if (kl >= lo && kl < hi) { sh4[0] = (unsigned)tid; sh4[1] = (unsigned)lo; }
        } else if (tid < 512) {
            int t2 = tid - 256;
            int* hs = same ? h0 : h1;
            int hi = hs[t2];
            int lo = t2 ? hs[t2 - 1] : 0;
            if (kh >= lo && kh < hi) { sh4[2] = (unsigned)t2; sh4[3] = (unsigned)lo; }
        }
        __syncthreads();
        plo |= sh4[0] << shift;  kl -= (int)sh4[1];
        phi |= sh4[2] << shift;  kh -= (int)sh4[3];
        pmask |= 255u << shift;
        __syncthreads();
    }
    unsigned int ulo0 = plo, uhi0 = phi;

    // ---- next-rank values for both quantiles in ONE pass ---------------------
    float clo = 0.f, chi = 0.f;
    unsigned int mlo = 0xFFFFFFFFu, mhi = 0xFFFFFFFFu;
#pragma unroll
    for (int j = 0; j < NEL / 1024; j++) {
        unsigned int u = uv[tid + j * 1024];
        if (u <= ulo0) clo += 1.f; else mlo = min(mlo, u);
        if (u <= uhi0) chi += 1.f; else mhi = min(mhi, u);
    }
    float cleL = blockSum1024(clo, sbuf, tid);
    float cleH = blockSum1024(chi, sbuf, tid);
    unsigned int mgtL = blockMin1024(mlo, (unsigned int*)sbuf, tid);
    unsigned int mgtH = blockMin1024(mhi, (unsigned int*)sbuf, tid);
    unsigned int ulo1 = (cleL >= (float)(ilo + 2)) ? ulo0 : mgtL;
    unsigned int uhi1 = (cleH >= (float)(ihi + 2)) ? uhi0 : mgtH;

    float vlo0 = key_to_float(ulo0), vlo1 = key_to_float(ulo1);
    float vhi0 = key_to_float(uhi0), vhi1 = key_to_float(uhi1);
    float qlo = vlo0 + flo * (vlo1 - vlo0);
    float qhi = vhi0 + fhi * (vhi1 - vhi0);

    // ---- fused mask pass: cnt, sum, sumsq in one sweep ------------------------
    float lc = 0.f, ls = 0.f, lq = 0.f;
#pragma unroll
    for (int j = 0; j < NEL / 1024; j++) {
        float v = key_to_float(uv[tid + j * 1024]);
        if (v < qlo || v > qhi) { lc += 1.f; ls += v; lq = fmaf(v, v, lq); }
    }
    float cnt = blockSum1024(lc, sbuf, tid);
    float sum = blockSum1024(ls, sbuf, tid);
    float ssq = blockSum1024(lq, sbuf, tid);

    if (cnt < 0.5f) {
        // fallback: full-array moments, then simple mask, then all
        float la = 0.f, lb = 0.f;
        for (int i = tid; i < NEL; i += T) {
            float v = key_to_float(uv[i]);
            la += v; lb = fmaf(v, v, lb);
        }
        float sumA = blockSum1024(la, sbuf, tid);
        float ssqA = blockSum1024(lb, sbuf, tid);
        float muA  = sumA / (float)NEL;
        float sdA  = sqrtf((ssqA - sumA * muA) / (float)(NEL - 1));
        lc = 0.f; ls = 0.f; lq = 0.f;
        for (int i = tid; i < NEL; i += T) {
            float v = key_to_float(uv[i]);
            if (fabsf(v - muA) > sdA) { lc += 1.f; ls += v; lq = fmaf(v, v, lq); }
        }
        cnt = blockSum1024(lc, sbuf, tid);
        sum = blockSum1024(ls, sbuf, tid);
        ssq = blockSum1024(lq, sbuf, tid);
        if (cnt < 0.5f) { cnt = (float)NEL; sum = sumA; ssq = ssqA; }
    }

    float ssd = ssq - sum * (sum / cnt);

    // ---- publish sigma; last block to finish computes the final output ------
    if (tid == 0) {
        g_sigma[arr] = sqrtf(ssd / (cnt - 1.0f));
        __threadfence();
        int done = atomicAdd(&g_done, 1);
        if (done == NARR - 1) {
            float acc = 0.f;
#pragma unroll
            for (int b = 0; b < NB; b++)
                acc += fmaxf(g_sigma[2 * b], g_sigma[2 * b + 1]);
            out[0] = acc * (1.0f / (float)NB);
            g_done = 0;           // reset for next graph replay
        }
    }
}

// ---------------------------------------------------------------------------
extern "C" void kernel_launch(void* const* d_in, const int* in_sizes, int n_in,
                              void* d_out, int out_size)
{
    const float* x = (const float*)d_in[0];
    const float* y = (const float*)d_in[1];
    float* out = (float*)d_out;
    (void)in_sizes; (void)n_in; (void)out_size;

    cudaFuncSetAttribute(fused_kernel,
                         cudaFuncAttributeMaxDynamicSharedMemorySize,
                         NEL * (int)sizeof(unsigned int));
    fused_kernel<<<GRIDN, 1024, NEL * sizeof(unsigned int)>>>(x, y, out);
}

// round 17
// speedup vs baseline: 1.2282x; 1.2282x over previous
#include <cuda_runtime.h>
#include <math.h>

#define NPTS   4096
#define NB     16
#define NARR   32           // 16 batches x 2 directions
#define D      3
#define NEL    (NPTS * D)   // 12288 residual elements per array
#define GR     14           // grid resolution per axis
#define NCELL  (GR * GR * GR)   // 2744
#define NCELLP 3072             // padded to 3*1024 for the scan
#define GRIDN  128          // persistent-kernel grid size (co-resident)

// Scratch (device globals only; no allocation allowed)
__device__ float4       g_sorted[(size_t)NARR * NPTS];      // {x,y,z,_}
__device__ int          g_cellstart[(size_t)NARR * (NCELL + 1)];
__device__ unsigned int g_keys[(size_t)NARR * NEL];         // SoA radix keys
__device__ float        g_sigma[NARR];
__device__ unsigned int g_bar[2];                           // ticket barriers
__device__ int          g_done;                             // self-reset

// ---------------------------------------------------------------------------
// Replay-safe device-wide barrier (monotonic tickets, no reset needed).
// ---------------------------------------------------------------------------
__device__ __forceinline__ void grid_barrier(unsigned int* bar)
{
    __syncthreads();
    if (threadIdx.x == 0) {
        __threadfence();
        unsigned int ticket = atomicAdd(bar, 1u);
        unsigned int target = ticket - (ticket % GRIDN) + GRIDN;
        while (*((volatile unsigned int*)bar) < target) __nanosleep(32);
        __threadfence();
    }
    __syncthreads();
}

// ---------------------------------------------------------------------------
// Block reductions for 1024 threads (32 warps)
// ---------------------------------------------------------------------------
__device__ __forceinline__ float blockSum1024(float v, float* sb, int tid)
{
#pragma unroll
    for (int o = 16; o; o >>= 1) v += __shfl_down_sync(0xffffffffu, v, o);
    if ((tid & 31) == 0) sb[tid >> 5] = v;
    __syncthreads();
    if (tid < 32) {
        float w = sb[tid];
#pragma unroll
        for (int o = 16; o; o >>= 1) w += __shfl_down_sync(0xffffffffu, w, o);
        if (tid == 0) sb[0] = w;
    }
    __syncthreads();
    float r = sb[0];
    __syncthreads();
    return r;
}

__device__ __forceinline__ unsigned int blockMin1024(unsigned int v,
                                                     unsigned int* sb, int tid)
{
#pragma unroll
    for (int o = 16; o; o >>= 1)
        v = min(v, __shfl_down_sync(0xffffffffu, v, o));
    if ((tid & 31) == 0) sb[tid >> 5] = v;
    __syncthreads();
    if (tid < 32) {
        unsigned int w = sb[tid];
#pragma unroll
        for (int o = 16; o; o >>= 1)
            w = min(w, __shfl_down_sync(0xffffffffu, w, o));
        if (tid == 0) sb[0] = w;
    }
    __syncthreads();
    unsigned int r = sb[0];
    __syncthreads();
    return r;
}

__device__ __forceinline__ float key_to_float(unsigned int u)
{
    u = (u & 0x80000000u) ? (u ^ 0x80000000u) : ~u;
    return __uint_as_float(u);
}

__device__ __forceinline__ void scan256(int* hh, int lane)
{
    int base = lane * 8;
    int loc[8];
    int s = 0;
#pragma unroll
    for (int j = 0; j < 8; j++) { s += hh[base + j]; loc[j] = s; }
    int incl = s;
#pragma unroll
    for (int o = 1; o < 32; o <<= 1) {
        int up = __shfl_up_sync(0xffffffffu, incl, o);
        if (lane >= o) incl += up;
    }
    int excl = incl - s;
#pragma unroll
    for (int j = 0; j < 8; j++) hh[base + j] = loc[j] + excl;
}

// ---------------------------------------------------------------------------
// ONE persistent kernel: Phase A build (blocks 0..31) | barrier |
// Phase B query (all 128 blocks, 1 query/thread) | barrier |
// Phase C robust std (blocks 0..31) + atomic finalize.   [R14 skeleton, GR=14]
// ---------------------------------------------------------------------------
__global__ __launch_bounds__(1024) void fused_kernel(
    const float* __restrict__ x, const float* __restrict__ y,
    float* __restrict__ out)
{
    extern __shared__ unsigned int uv[];     // 48KB, Phase C keys
    __shared__ int s_cnt[NCELLP];            // 12KB, Phase A histogram (padded)
    __shared__ int s_wsum[32];
    __shared__ int h0[256], h1[256];
    __shared__ float sbuf[32];
    __shared__ volatile unsigned int sh4[4];

    const int tid = threadIdx.x;             // 1024 threads
    const int blk = blockIdx.x;              // 0..127

    // ======================= Phase A: build grids ============================
    if (blk < NARR) {
        const int set   = blk;
        const int batch = set >> 1;
        const int which = set & 1;
        const float* P = ((which == 0) ? x : y) + (size_t)batch * NPTS * D;

#pragma unroll
        for (int j = 0; j < 3; j++) s_cnt[tid + j * 1024] = 0;
        __syncthreads();

        float3 pt[4];
        int    cid[4];
#pragma unroll
        for (int j = 0; j < 4; j++) {
            int i = tid + j * 1024;
            float px = P[3 * i], py = P[3 * i + 1], pz = P[3 * i + 2];
            pt[j] = make_float3(px, py, pz);
            int cx = min(GR - 1, max(0, (int)(px * (float)GR)));
            int cy = min(GR - 1, max(0, (int)(py * (float)GR)));
            int cz = min(GR - 1, max(0, (int)(pz * (float)GR)));
            cid[j] = (cz * GR + cy) * GR + cx;
            atomicAdd(&s_cnt[cid[j]], 1);
        }
        __syncthreads();

        // exclusive scan of s_cnt[NCELLP]: 3 elems/thread + warp scan + sums
        const int base = tid * 3;
        int loc[3];
        int s = 0;
#pragma unroll
        for (int j = 0; j < 3; j++) { int v = s_cnt[base + j]; loc[j] = s; s += v; }
        int incl = s;
#pragma unroll
        for (int o = 1; o < 32; o <<= 1) {
            int u = __shfl_up_sync(0xffffffffu, incl, o);
            if ((tid & 31) >= o) incl += u;
        }
        if ((tid & 31) == 31) s_wsum[tid >> 5] = incl;
        __syncthreads();
        if (tid < 32) {
            int v = s_wsum[tid];
#pragma unroll
            for (int o = 1; o < 32; o <<= 1) {
                int u = __shfl_up_sync(0xffffffffu, v, o);
                if (tid >= o) v += u;
            }
            s_wsum[tid] = v;
        }
        __syncthreads();
        int wexcl = (tid >= 32) ? s_wsum[(tid >> 5) - 1] : 0;
        int texcl = (incl - s) + wexcl;
        __syncthreads();
#pragma unroll
        for (int j = 0; j < 3; j++) s_cnt[base + j] = texcl + loc[j];
        __syncthreads();

        const int gbase = set * (NCELL + 1);
#pragma unroll
        for (int j = 0; j < 3; j++) {
            int i = tid + j * 1024;
            if (i < NCELL) g_cellstart[gbase + i] = s_cnt[i];
        }
        if (tid == 0) g_cellstart[gbase + NCELL] = NPTS;
        __syncthreads();

#pragma unroll
        for (int j = 0; j < 4; j++) {
            int off = atomicAdd(&s_cnt[cid[j]], 1);
            g_sorted[(size_t)set * NPTS + off] =
                make_float4(pt[j].x, pt[j].y, pt[j].z, 0.f);
        }
    }

    grid_barrier(&g_bar[0]);

    // ======================= Phase B: grid NN query ==========================
    {
        const int gtid = blk * 1024 + tid;        // 0..131071
        const int arr  = gtid >> 12;              // /NPTS
        const int i    = gtid & (NPTS - 1);       // sorted query index
        const int tset = arr ^ 1;

        float4 q = g_sorted[(size_t)arr * NPTS + i];
        const float4* __restrict__ T  = g_sorted + (size_t)tset * NPTS;
        const int* __restrict__    cs = g_cellstart + (size_t)tset * (NCELL + 1);

        const int cx = min(GR - 1, max(0, (int)(q.x * (float)GR)));
        const int cy = min(GR - 1, max(0, (int)(q.y * (float)GR)));
        const int cz = min(GR - 1, max(0, (int)(q.z * (float)GR)));

        const float h = 1.0f / (float)GR;
        float best = __int_as_float(0x7f800000);
        float bx = 0.f, by = 0.f, bz = 0.f;

        auto process = [&](float4 p) {
            float dx = q.x - p.x, dy = q.y - p.y, dz = q.z - p.z;
            float d2 = fmaf(dx, dx, fmaf(dy, dy, dz * dz));
            if (d2 < best) { best = d2; bx = p.x; by = p.y; bz = p.z; }
        };

        // merged rings 0+1: 3x3 rows, all bounds prefetched (MLP), with the
        // head point of each range software-pipelined (R14 pattern).
        {
            const int xlo = max(cx - 1, 0), xhi = min(cx + 1, GR - 1);
            int rs[10], re[9];
#pragma unroll
            for (int k = 0; k < 9; k++) {
                int dz = k / 3 - 1, dy = k % 3 - 1;
                int zz = cz + dz, yy = cy + dy;
                bool ok = (zz >= 0) && (zz < GR) && (yy >= 0) && (yy < GR);
                int rowb = (zz * GR + yy) * GR;
                rs[k] = ok ? cs[rowb + xlo] : 0;
                re[k] = ok ? cs[rowb + xhi + 1] : 0;
            }
            rs[9] = rs[8];                               // pipeline pad

            float4 head = T[min(rs[0], NPTS - 1)];       // in flight
#pragma unroll
            for (int k = 0; k < 9; k++) {
                float4 cur = head;
                head = T[min(rs[k + 1], NPTS - 1)];      // next head in flight
                if (rs[k] < re[k]) process(cur);
                for (int j = rs[k] + 1; j < re[k]; j++) process(T[j]);
            }
        }

        // rare fallback: rings r >= 2
        if (best > h * h) {
            for (int r = 2; r < GR; r++) {
                int zlo = max(cz - r, 0), zhi = min(cz + r, GR - 1);
                int xlo = max(cx - r, 0), xhi = min(cx + r, GR - 1);
                for (int zz = zlo; zz <= zhi; zz++) {
                    bool zface = (zz == cz - r) || (zz == cz + r);
                    int ylo = max(cy - r, 0), yhi = min(cy + r, GR - 1);
                    for (int yy = ylo; yy <= yhi; yy++) {
                        bool yface = (yy == cy - r) || (yy == cy + r);
                        int rowb = (zz * GR + yy) * GR;
                        if (zface || yface) {
                            int s0 = cs[rowb + xlo], s1 = cs[rowb + xhi + 1];
                            for (int j = s0; j < s1; j++) process(T[j]);
                        } else {
                            int xm = cx - r;
                            if (xm >= 0) {
                                int s0 = cs[rowb + xm], s1 = cs[rowb + xm + 1];
                                for (int j = s0; j < s1; j++) process(T[j]);
                            }
                            int xp = cx + r;
                            if (xp <= GR - 1) {
                                int s0 = cs[rowb + xp], s1 = cs[rowb + xp + 1];
                                for (int j = s0; j < s1; j++) process(T[j]);
                            }
                        }
                    }
                }
                float bnd = (float)r * h;
                if (best <= bnd * bnd) break;
            }
        }

        // residual -> order-preserving radix keys, SoA coalesced stores
        unsigned int ux = __float_as_uint(q.x - bx);
        unsigned int uy = __float_as_uint(q.y - by);
        unsigned int uz = __float_as_uint(q.z - bz);
        ux = (ux & 0x80000000u) ? ~ux : (ux | 0x80000000u);
        uy = (uy & 0x80000000u) ? ~uy : (uy | 0x80000000u);
        uz = (uz & 0x80000000u) ? ~uz : (uz | 0x80000000u);
        unsigned int* gk = g_keys + (size_t)arr * NEL;
        gk[0 * NPTS + i] = ux;
        gk[1 * NPTS + i] = uy;
        gk[2 * NPTS + i] = uz;
    }

    grid_barrier(&g_bar[1]);

    if (blk >= NARR) return;

    // ======================= Phase C: robust masked std ======================
    const int arr = blk;
    const int T   = 1024;
    const unsigned int* gk = g_keys + (size_t)arr * NEL;

#pragma unroll
    for (int j = 0; j < NEL / 1024; j++) {
        int i = tid + j * 1024;
        uv[i] = gk[i];
    }
    __syncthreads();

    const float n1 = (float)(NEL - 1);
    float hlo = 0.15f * n1;  int ilo = (int)hlo;  float flo = hlo - (float)ilo;
    float hhi = 0.85f * n1;  int ihi = (int)hhi;  float fhi = hhi - (float)ihi;

    // ---- dual-rank radix select ----------------------------------------------
    unsigned int plo = 0, phi = 0, pmask = 0;
    int kl = ilo, kh = ihi;
    for (int shift = 24; shift >= 0; shift -= 8) {
        bool same = (plo == phi);
        if (tid < 256) { h0[tid] = 0; h1[tid] = 0; }
        __syncthreads();
#pragma unroll
        for (int j = 0; j < NEL / 1024; j++) {
            unsigned int u = uv[tid + j * 1024];
            if ((u & pmask) == plo) atomicAdd(&h0[(u >> shift) & 255], 1);
            if (!same && (u & pmask) == phi)
                atomicAdd(&h1[(u >> shift) & 255], 1);
        }
        __syncthreads();
        if (tid < 32) scan256(h0, tid);
        else if (tid < 64 && !same) scan256(h1, tid - 32);
        __syncthreads();
        if (tid < 256) {
            int hi = h0[tid];
            int lo = tid ? h0[tid - 1] : 0;
            if (kl >= lo && kl < hi) { sh4[0] = (unsigned)tid; sh4[1] = (unsigned)lo; }
        } else if (tid < 512) {
            int t2 = tid - 256;
            int* hs = same ? h0 : h1;
            int hi = hs[t2];
            int lo = t2 ? hs[t2 - 1] : 0;
            if (kh >= lo && kh < hi) { sh4[2] = (unsigned)t2; sh4[3] = (unsigned)lo; }
        }
        __syncthreads();
        plo |= sh4[0] << shift;  kl -= (int)sh4[1];
        phi |= sh4[2] << shift;  kh -= (int)sh4[3];
        pmask |= 255u << shift;
        __syncthreads();
    }
    unsigned int ulo0 = plo, uhi0 = phi;

    // ---- next-rank values for both quantiles in ONE pass ---------------------
    float clo = 0.f, chi = 0.f;
    unsigned int mlo = 0xFFFFFFFFu, mhi = 0xFFFFFFFFu;
#pragma unroll
    for (int j = 0; j < NEL / 1024; j++) {
        unsigned int u = uv[tid + j * 1024];
        if (u <= ulo0) clo += 1.f; else mlo = min(mlo, u);
        if (u <= uhi0) chi += 1.f; else mhi = min(mhi, u);
    }
    float cleL = blockSum1024(clo, sbuf, tid);
    float cleH = blockSum1024(chi, sbuf, tid);
    unsigned int mgtL = blockMin1024(mlo, (unsigned int*)sbuf, tid);
    unsigned int mgtH = blockMin1024(mhi, (unsigned int*)sbuf, tid);
    unsigned int ulo1 = (cleL >= (float)(ilo + 2)) ? ulo0 : mgtL;
    unsigned int uhi1 = (cleH >= (float)(ihi + 2)) ? uhi0 : mgtH;

    float vlo0 = key_to_float(ulo0), vlo1 = key_to_float(ulo1);
    float vhi0 = key_to_float(uhi0), vhi1 = key_to_float(uhi1);
    float qlo = vlo0 + flo * (vlo1 - vlo0);
    float qhi = vhi0 + fhi * (vhi1 - vhi0);

    // ---- fused mask pass: cnt, sum, sumsq in one sweep ------------------------
    float lc = 0.f, ls = 0.f, lq = 0.f;
#pragma unroll
    for (int j = 0; j < NEL / 1024; j++) {
        float v = key_to_float(uv[tid + j * 1024]);
        if (v < qlo || v > qhi) { lc += 1.f; ls += v; lq = fmaf(v, v, lq); }
    }
    float cnt = blockSum1024(lc, sbuf, tid);
    float sum = blockSum1024(ls, sbuf, tid);
    float ssq = blockSum1024(lq, sbuf, tid);

    if (cnt < 0.5f) {
        // fallback: full-array moments, then simple mask, then all
        float la = 0.f, lb = 0.f;
        for (int i = tid; i < NEL; i += T) {
            float v = key_to_float(uv[i]);
            la += v; lb = fmaf(v, v, lb);
        }
        float sumA = blockSum1024(la, sbuf, tid);
        float ssqA = blockSum1024(lb, sbuf, tid);
        float muA  = sumA / (float)NEL;
        float sdA  = sqrtf((ssqA - sumA * muA) / (float)(NEL - 1));
        lc = 0.f; ls = 0.f; lq = 0.f;
        for (int i = tid; i < NEL; i += T) {
            float v = key_to_float(uv[i]);
            if (fabsf(v - muA) > sdA) { lc += 1.f; ls += v; lq = fmaf(v, v, lq); }
        }
        cnt = blockSum1024(lc, sbuf, tid);
        sum = blockSum1024(ls, sbuf, tid);
        ssq = blockSum1024(lq, sbuf, tid);
        if (cnt < 0.5f) { cnt = (float)NEL; sum = sumA; ssq = ssqA; }
    }

    float ssd = ssq - sum * (sum / cnt);

    // ---- publish sigma; last block to finish computes the final output ------
    if (tid == 0) {
        g_sigma[arr] = sqrtf(ssd / (cnt - 1.0f));
        __threadfence();
        int done = atomicAdd(&g_done, 1);
        if (done == NARR - 1) {
            float acc = 0.f;
#pragma unroll
            for (int b = 0; b < NB; b++)
                acc += fmaxf(g_sigma[2 * b], g_sigma[2 * b + 1]);
            out[0] = acc * (1.0f / (float)NB);
            g_done = 0;           // reset for next graph replay
        }
    }
}

// ---------------------------------------------------------------------------
extern "C" void kernel_launch(void* const* d_in, const int* in_sizes, int n_in,
                              void* d_out, int out_size)
{
    const float* x = (const float*)d_in[0];
    const float* y = (const float*)d_in[1];
    float* out = (float*)d_out;
    (void)in_sizes; (void)n_in; (void)out_size;

    cudaFuncSetAttribute(fused_kernel,
                         cudaFuncAttributeMaxDynamicSharedMemorySize,
                         NEL * (int)sizeof(unsigned int));
    fused_kernel<<<GRIDN, 1024, NEL * sizeof(unsigned int)>>>(x, y, out);
}